// round 16
// baseline (speedup 1.0000x reference)
#include <cuda_runtime.h>
#include <cuda_bf16.h>
#include <cstdint>

#define BB   8192
#define DD   128
#define NN   16384
#define L2E5 7.21347520444482f   // 5 * log2(e)
#define SROW2 40                 // chunk row: 32 data + 8 pad shorts
#define BUFB  10240              // one chunk buffer: 128*40*2 bytes

// ---------------- device scratch ----------------
__device__ __align__(16) __nv_bfloat16 g_hi[(size_t)NN * DD];   // normalized bf16
__device__ __align__(16) __nv_bfloat16 g_sc[(size_t)NN * DD];   // normalized * 5*log2(e)
__device__ unsigned g_rm[NN];
__device__ int      g_hq[NN];
__device__ double   g_denom;
__device__ double   g_pos;
__device__ int      g_is64;

// bf16 tensor-core mma (sm_80+ baseline PTX)
__device__ __forceinline__ void mma16816(float* c, const uint32_t* a, const uint32_t* b) {
    asm volatile(
        "mma.sync.aligned.m16n8k16.row.col.f32.bf16.bf16.f32 "
        "{%0,%1,%2,%3}, {%4,%5,%6,%7}, {%8,%9}, {%0,%1,%2,%3};"
        : "+f"(c[0]), "+f"(c[1]), "+f"(c[2]), "+f"(c[3])
        : "r"(a[0]), "r"(a[1]), "r"(a[2]), "r"(a[3]), "r"(b[0]), "r"(b[1]));
}
__device__ __forceinline__ void ldsm4(uint32_t& r0, uint32_t& r1, uint32_t& r2, uint32_t& r3,
                                      uint32_t addr) {
    asm volatile("ldmatrix.sync.aligned.m8n8.x4.shared.b16 {%0,%1,%2,%3}, [%4];"
                 : "=r"(r0), "=r"(r1), "=r"(r2), "=r"(r3) : "r"(addr));
}
__device__ __forceinline__ uint32_t smem_u32(const void* p) {
    uint32_t a;
    asm("{ .reg .u64 t; cvta.to.shared.u64 t, %1; cvt.u32.u64 %0, t; }" : "=r"(a) : "l"(p));
    return a;
}
__device__ __forceinline__ void cpa16(uint32_t d, const void* s) {
    asm volatile("cp.async.cg.shared.global [%0], [%1], 16;" :: "r"(d), "l"(s) : "memory");
}
#define CPA_COMMIT() asm volatile("cp.async.commit_group;" ::: "memory")
#define CPA_WAIT(n)  asm volatile("cp.async.wait_group %0;" :: "n"(n) : "memory")
__device__ __forceinline__ float ex2f(float x) {
    float r;
    asm("ex2.approx.f32 %0, %1;" : "=f"(r) : "f"(x));
    return r;
}

// ---------------- init: zero accumulators + detect int32 vs int64 --------
__global__ void k_init(const int* __restrict__ nq32) {
    int found = 0;
    for (int w = 2 * threadIdx.x + 1; w < 4096; w += 512)
        found |= (nq32[w] != 0);
    int any = __syncthreads_or(found);
    if (threadIdx.x == 0) {
        g_is64  = !any;
        g_denom = 0.0;
        g_pos   = 0.0;
    }
}

// ---------------- normalize + bf16 round (+ scaled copy) + pos dot --------
__global__ void k_norm(const float* __restrict__ x, const float* __restrict__ xa) {
    int r = blockIdx.x;
    int t = threadIdx.x;                         // 0..127
    float xv = x[(size_t)r * DD + t];
    float av = xa[(size_t)r * DD + t];
    float sx = xv * xv, sa = av * av, sd = xv * av;
    #pragma unroll
    for (int o = 16; o; o >>= 1) {
        sx += __shfl_xor_sync(0xFFFFFFFFu, sx, o);
        sa += __shfl_xor_sync(0xFFFFFFFFu, sa, o);
        sd += __shfl_xor_sync(0xFFFFFFFFu, sd, o);
    }
    __shared__ float wsx[4], wsa[4], wsd[4];
    int w = t >> 5, l = t & 31;
    if (l == 0) { wsx[w] = sx; wsa[w] = sa; wsd[w] = sd; }
    __syncthreads();
    sx = wsx[0] + wsx[1] + wsx[2] + wsx[3];
    sa = wsa[0] + wsa[1] + wsa[2] + wsa[3];
    sd = wsd[0] + wsd[1] + wsd[2] + wsd[3];
    float inx = rsqrtf(sx), ina = rsqrtf(sa);

    float v1 = xv * inx, v2 = av * ina;
    g_hi[(size_t)r * DD + t]        = __float2bfloat16(v1);
    g_hi[(size_t)(BB + r) * DD + t] = __float2bfloat16(v2);
    g_sc[(size_t)r * DD + t]        = __float2bfloat16(v1 * L2E5);
    g_sc[(size_t)(BB + r) * DD + t] = __float2bfloat16(v2 * L2E5);
    if (t == 0) atomicAdd(&g_pos, (double)(sd * inx * ina));
}

// ---------------- cluster masks -------------------------------------------
__global__ void k_mask(const void* __restrict__ hq, const void* __restrict__ nq, int K) {
    int n = blockIdx.x * blockDim.x + threadIdx.x;
    if (n >= NN) return;
    int is64 = g_is64;
    int hv = is64 ? (int)((const long long*)hq)[n] : ((const int*)hq)[n];
    unsigned m = 0;
    for (int k = 0; k < K; k++) {
        int v = is64 ? (int)((const long long*)nq)[(size_t)n * K + k]
                     : ((const int*)nq)[(size_t)n * K + k];
        m |= (1u << (v & 31));
    }
    g_hq[n] = hv & 31;
    g_rm[n] = m;
}

// ---------------- fused GEMM(HMMA) + exp + masked sum (upper triangle) ----
// Block 128x128, 256 thr = 8 warps (2m x 4n), warp tile 64x32.
// A = g_sc (pre-scaled), B = g_hi -> acc is the ex2 argument.
// K as 4 chunks of 32, cp.async double-buffered. Predicated-add epilogue.
__global__ void __launch_bounds__(256, 2) k_main() {
    int bi = blockIdx.y, bj = blockIdx.x;
    if (bj < bi) return;                       // symmetric: only bj >= bi

    __shared__ __align__(16) unsigned short As2[2][128][SROW2];
    __shared__ __align__(16) unsigned short Bs2[2][128][SROW2];
    __shared__ unsigned rmI[128], rmJ[128];
    __shared__ unsigned char hqI[128], hqJ[128];
    __shared__ float    red[8];

    int tid  = threadIdx.x;
    int wid  = tid >> 5, lane = tid & 31;
    int wm   = wid & 1,  wn   = wid >> 1;      // 2 m-slices x 4 n-slices
    int g    = lane >> 2, t4  = lane & 3;

    if (tid < 128) {
        rmI[tid] = g_rm[bi * 128 + tid];
        hqI[tid] = (unsigned char)g_hq[bi * 128 + tid];
    } else {
        int t = tid - 128;
        rmJ[t] = g_rm[bj * 128 + t];
        hqJ[t] = (unsigned char)g_hq[bj * 128 + t];
    }

    float acc[4][4][4];                        // [mb][nb][reg]
    #pragma unroll
    for (int mb = 0; mb < 4; mb++)
        #pragma unroll
        for (int nb = 0; nb < 4; nb++)
            #pragma unroll
            for (int r = 0; r < 4; r++) acc[mb][nb][r] = 0.f;

    const uint4* Agl = (const uint4*)(g_sc + (size_t)bi * 128 * DD);
    const uint4* Bgl = (const uint4*)(g_hi + (size_t)bj * 128 * DD);
    uint32_t smA = smem_u32(&As2[0][0][0]);
    uint32_t smB = smem_u32(&Bs2[0][0][0]);

    int m0 = wm * 64, n0 = wn * 32;
    uint32_t arow = smA + (uint32_t)((m0 + (lane & 15)) * (SROW2 * 2))
                  + (uint32_t)((lane >> 4) << 4);
    uint32_t brow = smB + (uint32_t)((n0 + ((lane >> 4) << 3) + (lane & 7)) * (SROW2 * 2))
                  + (uint32_t)(((lane >> 3) & 1) << 4);

    // async-load one 32-col chunk (c) into buffer (f); 256 threads
    #define LOAD_CHUNK(c, f)                                              \
        do {                                                              \
            _Pragma("unroll")                                             \
            for (int it = 0; it < 2; it++) {                              \
                int idx = tid + it * 256;                                 \
                int rr2 = idx >> 2, qq = idx & 3;                         \
                uint32_t off = (uint32_t)(f) * BUFB                       \
                             + (uint32_t)(rr2 * (SROW2 * 2) + qq * 16);   \
                cpa16(smA + off, Agl + rr2 * 16 + (c) * 4 + qq);          \
                cpa16(smB + off, Bgl + rr2 * 16 + (c) * 4 + qq);          \
            }                                                             \
            CPA_COMMIT();                                                 \
        } while (0)

    LOAD_CHUNK(0, 0);

    #pragma unroll
    for (int c = 0; c < 4; c++) {
        if (c < 3) {
            LOAD_CHUNK(c + 1, (c + 1) & 1);
            CPA_WAIT(1);
        } else {
            CPA_WAIT(0);
        }
        __syncthreads();
        uint32_t boff = (uint32_t)(c & 1) * BUFB;
        #pragma unroll
        for (int ks = 0; ks < 2; ks++) {
            uint32_t koff = boff + (uint32_t)(ks * 32);
            uint32_t b[4][2];
            #pragma unroll
            for (int nbp = 0; nbp < 2; nbp++)
                ldsm4(b[2 * nbp][0], b[2 * nbp][1], b[2 * nbp + 1][0], b[2 * nbp + 1][1],
                      brow + (uint32_t)(nbp * 16 * (SROW2 * 2)) + koff);
            uint32_t a[4][4];
            #pragma unroll
            for (int mb = 0; mb < 4; mb++)
                ldsm4(a[mb][0], a[mb][1], a[mb][2], a[mb][3],
                      arow + (uint32_t)(mb * 16 * (SROW2 * 2)) + koff);
            #pragma unroll
            for (int mb = 0; mb < 4; mb++)
                #pragma unroll
                for (int nb = 0; nb < 4; nb++)
                    mma16816(acc[mb][nb], a[mb], b[nb]);
        }
        __syncthreads();
    }
    #undef LOAD_CHUNK

    // ---- epilogue: predicated adds; per-row masks in registers ----
    unsigned rmi8[8], mr8[8];
    float    t8[8];
    #pragma unroll
    for (int mb = 0; mb < 4; mb++)
        #pragma unroll
        for (int rr = 0; rr < 2; rr++) {
            int k = mb * 2 + rr;
            int row = m0 + mb * 16 + g + rr * 8;
            rmi8[k] = rmI[row];
            mr8[k]  = 1u << hqI[row];
            t8[k]   = 0.f;
        }

    if (bi != bj) {
        #pragma unroll
        for (int nb = 0; nb < 4; nb++)
            #pragma unroll
            for (int rc = 0; rc < 2; rc++) {
                int col = n0 + nb * 8 + 2 * t4 + rc;
                unsigned rmj = rmJ[col];
                unsigned mc  = 1u << hqJ[col];
                #pragma unroll
                for (int k = 0; k < 8; k++) {
                    float e = ex2f(acc[k >> 1][nb][(k & 1) * 2 + rc]);
                    if (rmi8[k] & mc)  t8[k] += e;
                    if (rmj & mr8[k])  t8[k] += e;
                }
            }
    } else {
        #pragma unroll
        for (int nb = 0; nb < 4; nb++)
            #pragma unroll
            for (int rc = 0; rc < 2; rc++) {
                int col = n0 + nb * 8 + 2 * t4 + rc;
                unsigned rmj = rmJ[col];
                unsigned mc  = 1u << hqJ[col];
                #pragma unroll
                for (int k = 0; k < 8; k++) {
                    int row = m0 + (k >> 1) * 16 + g + (k & 1) * 8;
                    if (row < col) {
                        float e = ex2f(acc[k >> 1][nb][(k & 1) * 2 + rc]);
                        if (rmi8[k] & mc)  t8[k] += e;
                        if (rmj & mr8[k])  t8[k] += e;
                    }
                }
            }
    }

    float tsum = ((t8[0] + t8[1]) + (t8[2] + t8[3]))
               + ((t8[4] + t8[5]) + (t8[6] + t8[7]));
    #pragma unroll
    for (int o = 16; o; o >>= 1) tsum += __shfl_xor_sync(0xFFFFFFFFu, tsum, o);
    if (lane == 0) red[wid] = tsum;
    __syncthreads();
    if (tid == 0) {
        float s = 0.f;
        #pragma unroll
        for (int w = 0; w < 8; w++) s += red[w];
        atomicAdd(&g_denom, (double)s);
    }
}

// ---------------- finalize -------------------------------------------------
__global__ void k_fin(float* out) {
    if (threadIdx.x == 0)
        out[0] = (float)(log(g_denom) - g_pos / ((double)BB * 0.2));
}

// ---------------- launch ---------------------------------------------------
extern "C" void kernel_launch(void* const* d_in, const int* in_sizes, int n_in,
                              void* d_out, int out_size) {
    const float* x  = (const float*)d_in[0];
    const float* xa = (const float*)d_in[1];
    const void*  hq = d_in[2];
    const void*  nq = d_in[3];
    int K = in_sizes[3] / NN;                 // 10

    k_init<<<1, 256>>>((const int*)nq);
    k_norm<<<BB, 128>>>(x, xa);
    k_mask<<<(NN + 255) / 256, 256>>>(hq, nq, K);
    k_main<<<dim3(128, 128), 256>>>();
    k_fin<<<1, 32>>>((float*)d_out);
}

// round 17
// speedup vs baseline: 1.0799x; 1.0799x over previous
#include <cuda_runtime.h>
#include <cuda_bf16.h>
#include <cstdint>

#define BB   8192
#define DD   128
#define NN   16384
#define L2E5 7.21347520444482f   // 5 * log2(e)
#define SROW2 40                 // chunk row: 32 data + 8 pad shorts (80B)
#define BUFA  10240              // A chunk buffer: 128*40*2
#define BUFB2 5120               // B chunk buffer: 64*40*2

// ---------------- device scratch ----------------
__device__ __align__(16) __nv_bfloat16 g_hi[(size_t)NN * DD];   // normalized bf16
__device__ __align__(16) __nv_bfloat16 g_sc[(size_t)NN * DD];   // normalized * 5*log2(e)
__device__ unsigned g_rm[NN];
__device__ int      g_hq[NN];
__device__ double   g_denom;
__device__ double   g_pos;
__device__ int      g_is64;

// bf16 tensor-core mma (sm_80+ baseline PTX)
__device__ __forceinline__ void mma16816(float* c, const uint32_t* a, const uint32_t* b) {
    asm volatile(
        "mma.sync.aligned.m16n8k16.row.col.f32.bf16.bf16.f32 "
        "{%0,%1,%2,%3}, {%4,%5,%6,%7}, {%8,%9}, {%0,%1,%2,%3};"
        : "+f"(c[0]), "+f"(c[1]), "+f"(c[2]), "+f"(c[3])
        : "r"(a[0]), "r"(a[1]), "r"(a[2]), "r"(a[3]), "r"(b[0]), "r"(b[1]));
}
__device__ __forceinline__ void ldsm4(uint32_t& r0, uint32_t& r1, uint32_t& r2, uint32_t& r3,
                                      uint32_t addr) {
    asm volatile("ldmatrix.sync.aligned.m8n8.x4.shared.b16 {%0,%1,%2,%3}, [%4];"
                 : "=r"(r0), "=r"(r1), "=r"(r2), "=r"(r3) : "r"(addr));
}
__device__ __forceinline__ uint32_t smem_u32(const void* p) {
    uint32_t a;
    asm("{ .reg .u64 t; cvta.to.shared.u64 t, %1; cvt.u32.u64 %0, t; }" : "=r"(a) : "l"(p));
    return a;
}
__device__ __forceinline__ void cpa16(uint32_t d, const void* s) {
    asm volatile("cp.async.cg.shared.global [%0], [%1], 16;" :: "r"(d), "l"(s) : "memory");
}
#define CPA_COMMIT() asm volatile("cp.async.commit_group;" ::: "memory")
#define CPA_WAIT(n)  asm volatile("cp.async.wait_group %0;" :: "n"(n) : "memory")
__device__ __forceinline__ float ex2f(float x) {
    float r;
    asm("ex2.approx.f32 %0, %1;" : "=f"(r) : "f"(x));
    return r;
}

// ---------------- init: zero accumulators + detect int32 vs int64 --------
__global__ void k_init(const int* __restrict__ nq32) {
    int found = 0;
    for (int w = 2 * threadIdx.x + 1; w < 4096; w += 512)
        found |= (nq32[w] != 0);
    int any = __syncthreads_or(found);
    if (threadIdx.x == 0) {
        g_is64  = !any;
        g_denom = 0.0;
        g_pos   = 0.0;
    }
}

// ---------------- normalize + bf16 round (+ scaled copy) + pos dot --------
__global__ void k_norm(const float* __restrict__ x, const float* __restrict__ xa) {
    int r = blockIdx.x;
    int t = threadIdx.x;                         // 0..127
    float xv = x[(size_t)r * DD + t];
    float av = xa[(size_t)r * DD + t];
    float sx = xv * xv, sa = av * av, sd = xv * av;
    #pragma unroll
    for (int o = 16; o; o >>= 1) {
        sx += __shfl_xor_sync(0xFFFFFFFFu, sx, o);
        sa += __shfl_xor_sync(0xFFFFFFFFu, sa, o);
        sd += __shfl_xor_sync(0xFFFFFFFFu, sd, o);
    }
    __shared__ float wsx[4], wsa[4], wsd[4];
    int w = t >> 5, l = t & 31;
    if (l == 0) { wsx[w] = sx; wsa[w] = sa; wsd[w] = sd; }
    __syncthreads();
    sx = wsx[0] + wsx[1] + wsx[2] + wsx[3];
    sa = wsa[0] + wsa[1] + wsa[2] + wsa[3];
    sd = wsd[0] + wsd[1] + wsd[2] + wsd[3];
    float inx = rsqrtf(sx), ina = rsqrtf(sa);

    float v1 = xv * inx, v2 = av * ina;
    g_hi[(size_t)r * DD + t]        = __float2bfloat16(v1);
    g_hi[(size_t)(BB + r) * DD + t] = __float2bfloat16(v2);
    g_sc[(size_t)r * DD + t]        = __float2bfloat16(v1 * L2E5);
    g_sc[(size_t)(BB + r) * DD + t] = __float2bfloat16(v2 * L2E5);
    if (t == 0) atomicAdd(&g_pos, (double)(sd * inx * ina));
}

// ---------------- cluster masks -------------------------------------------
__global__ void k_mask(const void* __restrict__ hq, const void* __restrict__ nq, int K) {
    int n = blockIdx.x * blockDim.x + threadIdx.x;
    if (n >= NN) return;
    int is64 = g_is64;
    int hv = is64 ? (int)((const long long*)hq)[n] : ((const int*)hq)[n];
    unsigned m = 0;
    for (int k = 0; k < K; k++) {
        int v = is64 ? (int)((const long long*)nq)[(size_t)n * K + k]
                     : ((const int*)nq)[(size_t)n * K + k];
        m |= (1u << (v & 31));
    }
    g_hq[n] = hv & 31;
    g_rm[n] = m;
}

// ---------------- fused GEMM(HMMA) + exp + masked sum (upper triangle) ----
// Block tile 128(m) x 64(n), 128 thr = 4 warps (2m x 2n), warp tile 64x32.
// 4 CTAs/SM for phase diversity. One __syncthreads per K-chunk.
// A = g_sc (pre-scaled), B = g_hi -> acc is the ex2 argument.
__global__ void __launch_bounds__(128, 4) k_main() {
    int bi = blockIdx.y, bj = blockIdx.x;          // bj: 64-col tiles (0..255)
    if (bj < 2 * bi) return;                       // keep cols >= row-tile start

    __shared__ __align__(16) unsigned short As2[2][128][SROW2];
    __shared__ __align__(16) unsigned short Bs2[2][64][SROW2];
    __shared__ unsigned rmI[128], rmJ[64];
    __shared__ unsigned char hqI[128], hqJ[64];
    __shared__ float    red[4];

    int tid  = threadIdx.x;
    int wid  = tid >> 5, lane = tid & 31;
    int wm   = wid & 1,  wn   = wid >> 1;          // 2m x 2n warps
    int g    = lane >> 2, t4  = lane & 3;

    rmI[tid] = g_rm[bi * 128 + tid];
    hqI[tid] = (unsigned char)g_hq[bi * 128 + tid];
    if (tid < 64) {
        rmJ[tid] = g_rm[bj * 64 + tid];
        hqJ[tid] = (unsigned char)g_hq[bj * 64 + tid];
    }

    float acc[4][4][4];                            // [mb][nb][reg] = 64 regs
    #pragma unroll
    for (int mb = 0; mb < 4; mb++)
        #pragma unroll
        for (int nb = 0; nb < 4; nb++)
            #pragma unroll
            for (int r = 0; r < 4; r++) acc[mb][nb][r] = 0.f;

    const uint4* Agl = (const uint4*)(g_sc + (size_t)bi * 128 * DD);
    const uint4* Bgl = (const uint4*)(g_hi + (size_t)bj * 64 * DD);
    uint32_t smA = smem_u32(&As2[0][0][0]);
    uint32_t smB = smem_u32(&Bs2[0][0][0]);

    int m0 = wm * 64, n0 = wn * 32;
    uint32_t arow = smA + (uint32_t)((m0 + (lane & 15)) * (SROW2 * 2))
                  + (uint32_t)((lane >> 4) << 4);
    uint32_t brow = smB + (uint32_t)((n0 + ((lane >> 4) << 3) + (lane & 7)) * (SROW2 * 2))
                  + (uint32_t)(((lane >> 3) & 1) << 4);

    // async-load one 32-col chunk (c) into buffer (f); 128 threads
    #define LOAD_CHUNK(c, f)                                              \
        do {                                                              \
            _Pragma("unroll")                                             \
            for (int it = 0; it < 4; it++) {                              \
                int idx = tid + it * 128;                                 \
                int rr2 = idx >> 2, qq = idx & 3;                         \
                cpa16(smA + (uint32_t)(f) * BUFA                          \
                          + (uint32_t)(rr2 * (SROW2 * 2) + qq * 16),      \
                      Agl + rr2 * 16 + (c) * 4 + qq);                     \
            }                                                             \
            _Pragma("unroll")                                             \
            for (int it = 0; it < 2; it++) {                              \
                int idx = tid + it * 128;                                 \
                int rr2 = idx >> 2, qq = idx & 3;                         \
                cpa16(smB + (uint32_t)(f) * BUFB2                         \
                          + (uint32_t)(rr2 * (SROW2 * 2) + qq * 16),      \
                      Bgl + rr2 * 16 + (c) * 4 + qq);                     \
            }                                                             \
            CPA_COMMIT();                                                 \
        } while (0)

    LOAD_CHUNK(0, 0);

    #pragma unroll
    for (int c = 0; c < 4; c++) {
        CPA_WAIT(0);                               // chunk c arrived
        __syncthreads();                           // publish c; retire readers of buf (c+1)&1
        if (c < 3) LOAD_CHUNK(c + 1, (c + 1) & 1); // flies during compute of c
        uint32_t aoff = (uint32_t)(c & 1) * BUFA;
        uint32_t boff = (uint32_t)(c & 1) * BUFB2;
        #pragma unroll
        for (int ks = 0; ks < 2; ks++) {
            uint32_t koff = (uint32_t)(ks * 32);
            uint32_t b[4][2];
            #pragma unroll
            for (int nbp = 0; nbp < 2; nbp++)
                ldsm4(b[2 * nbp][0], b[2 * nbp][1], b[2 * nbp + 1][0], b[2 * nbp + 1][1],
                      brow + boff + (uint32_t)(nbp * 16 * (SROW2 * 2)) + koff);
            uint32_t a[4][4];
            #pragma unroll
            for (int mb = 0; mb < 4; mb++)
                ldsm4(a[mb][0], a[mb][1], a[mb][2], a[mb][3],
                      arow + aoff + (uint32_t)(mb * 16 * (SROW2 * 2)) + koff);
            #pragma unroll
            for (int mb = 0; mb < 4; mb++)
                #pragma unroll
                for (int nb = 0; nb < 4; nb++)
                    mma16816(acc[mb][nb], a[mb], b[nb]);
        }
    }
    #undef LOAD_CHUNK

    // ---- epilogue: predicated adds; per-row masks in registers ----
    unsigned rmi8[8], mr8[8];
    float    t8[8];
    #pragma unroll
    for (int mb = 0; mb < 4; mb++)
        #pragma unroll
        for (int rr = 0; rr < 2; rr++) {
            int k = mb * 2 + rr;
            int row = m0 + mb * 16 + g + rr * 8;
            rmi8[k] = rmI[row];
            mr8[k]  = 1u << hqI[row];
            t8[k]   = 0.f;
        }

    bool straddle = (bj >> 1) == bi;               // tile can contain row >= col
    if (!straddle) {
        #pragma unroll
        for (int nb = 0; nb < 4; nb++)
            #pragma unroll
            for (int rc = 0; rc < 2; rc++) {
                int col = n0 + nb * 8 + 2 * t4 + rc;
                unsigned rmj = rmJ[col];
                unsigned mc  = 1u << hqJ[col];
                #pragma unroll
                for (int k = 0; k < 8; k++) {
                    float e = ex2f(acc[k >> 1][nb][(k & 1) * 2 + rc]);
                    if (rmi8[k] & mc)  t8[k] += e;
                    if (rmj & mr8[k])  t8[k] += e;
                }
            }
    } else {
        int rbase = bi * 128, cbase = bj * 64;
        #pragma unroll
        for (int nb = 0; nb < 4; nb++)
            #pragma unroll
            for (int rc = 0; rc < 2; rc++) {
                int col = n0 + nb * 8 + 2 * t4 + rc;
                unsigned rmj = rmJ[col];
                unsigned mc  = 1u << hqJ[col];
                int gcol = cbase + col;
                #pragma unroll
                for (int k = 0; k < 8; k++) {
                    int grow = rbase + m0 + (k >> 1) * 16 + g + (k & 1) * 8;
                    if (grow < gcol) {
                        float e = ex2f(acc[k >> 1][nb][(k & 1) * 2 + rc]);
                        if (rmi8[k] & mc)  t8[k] += e;
                        if (rmj & mr8[k])  t8[k] += e;
                    }
                }
            }
    }

    float tsum = ((t8[0] + t8[1]) + (t8[2] + t8[3]))
               + ((t8[4] + t8[5]) + (t8[6] + t8[7]));
    #pragma unroll
    for (int o = 16; o; o >>= 1) tsum += __shfl_xor_sync(0xFFFFFFFFu, tsum, o);
    if (lane == 0) red[wid] = tsum;
    __syncthreads();
    if (tid == 0)
        atomicAdd(&g_denom, (double)(red[0] + red[1] + red[2] + red[3]));
}

// ---------------- finalize -------------------------------------------------
__global__ void k_fin(float* out) {
    if (threadIdx.x == 0)
        out[0] = (float)(log(g_denom) - g_pos / ((double)BB * 0.2));
}

// ---------------- launch ---------------------------------------------------
extern "C" void kernel_launch(void* const* d_in, const int* in_sizes, int n_in,
                              void* d_out, int out_size) {
    const float* x  = (const float*)d_in[0];
    const float* xa = (const float*)d_in[1];
    const void*  hq = d_in[2];
    const void*  nq = d_in[3];
    int K = in_sizes[3] / NN;                 // 10

    k_init<<<1, 256>>>((const int*)nq);
    k_norm<<<BB, 128>>>(x, xa);
    k_mask<<<(NN + 255) / 256, 256>>>(hq, nq, K);
    k_main<<<dim3(256, 128), 128>>>();
    k_fin<<<1, 32>>>((float*)d_out);
}